// round 4
// baseline (speedup 1.0000x reference)
#include <cuda_runtime.h>
#include <cuda_bf16.h>

#define NN 50000
#define DD 128
#define EMAX 600000
#define LDS_PAD 136   // bf16 elems per smem row (conflict-mitigating pad)

// ------------- scratch (static device globals; no allocation) -------------
__device__ float          g_H[NN * DD];      // GEMM output, pre-scaled by dinv[row]
__device__ unsigned short g_Xh[NN * DD];     // activations, bf16 hi
__device__ unsigned short g_Xl[NN * DD];     // activations, bf16 lo
__device__ unsigned short g_Wh[3 * DD * DD]; // weights, bf16 hi (3 layers)
__device__ unsigned short g_Wl[3 * DD * DD]; // weights, bf16 lo
__device__ float g_dinv[NN];
__device__ int   g_cnt[NN];
__device__ int   g_rowptr[NN + 1];
__device__ int   g_cursor[NN];
__device__ int   g_srcs[EMAX];
__device__ int   g_flag;           // 1 => edge_index is int32, 0 => int64

// ------------------------------ helpers ------------------------------------
__device__ __forceinline__ void split4(float4 v, ushort4& h, ushort4& l) {
    float f[4] = {v.x, v.y, v.z, v.w};
    unsigned short hh[4], ll[4];
    #pragma unroll
    for (int i = 0; i < 4; i++) {
        __nv_bfloat16 b = __float2bfloat16(f[i]);
        hh[i] = __bfloat16_as_ushort(b);
        ll[i] = __bfloat16_as_ushort(__float2bfloat16(f[i] - __bfloat162float(b)));
    }
    h = make_ushort4(hh[0], hh[1], hh[2], hh[3]);
    l = make_ushort4(ll[0], ll[1], ll[2], ll[3]);
}

__device__ __forceinline__ void ldm_x4(unsigned int r[4], const unsigned short* p) {
    unsigned int addr = (unsigned int)__cvta_generic_to_shared(p);
    asm volatile("ldmatrix.sync.aligned.m8n8.x4.shared.b16 {%0,%1,%2,%3}, [%4];"
                 : "=r"(r[0]), "=r"(r[1]), "=r"(r[2]), "=r"(r[3]) : "r"(addr));
}

__device__ __forceinline__ void ldm_x4_t(unsigned int r[4], const unsigned short* p) {
    unsigned int addr = (unsigned int)__cvta_generic_to_shared(p);
    asm volatile("ldmatrix.sync.aligned.m8n8.x4.trans.shared.b16 {%0,%1,%2,%3}, [%4];"
                 : "=r"(r[0]), "=r"(r[1]), "=r"(r[2]), "=r"(r[3]) : "r"(addr));
}

__device__ __forceinline__ void mma16816(float c[4], const unsigned int a[4],
                                         unsigned int b0, unsigned int b1) {
    asm volatile(
        "mma.sync.aligned.m16n8k16.row.col.f32.bf16.bf16.f32 "
        "{%0,%1,%2,%3}, {%4,%5,%6,%7}, {%8,%9}, {%0,%1,%2,%3};"
        : "+f"(c[0]), "+f"(c[1]), "+f"(c[2]), "+f"(c[3])
        : "r"(a[0]), "r"(a[1]), "r"(a[2]), "r"(a[3]), "r"(b0), "r"(b1));
}

// --------------------------- preprocessing --------------------------------
// Fused: convert emb -> Xh/Xl, convert W1..W3 -> Wh/Wl, zero cnt, zero flag.
__global__ void k_pre(const float* __restrict__ emb,
                      const float* __restrict__ W1,
                      const float* __restrict__ W2,
                      const float* __restrict__ W3) {
    int t = blockIdx.x * blockDim.x + threadIdx.x;
    if (t < (NN * DD) / 4) {
        float4 v = ((const float4*)emb)[t];
        ushort4 h, l;
        split4(v, h, l);
        ((ushort4*)g_Xh)[t] = h;
        ((ushort4*)g_Xl)[t] = l;
    }
    if (t < 3 * (DD * DD / 4)) {
        int wi = t / (DD * DD / 4);
        int i = t - wi * (DD * DD / 4);
        const float* W = (wi == 0) ? W1 : (wi == 1 ? W2 : W3);
        float4 v = ((const float4*)W)[i];
        ushort4 h, l;
        split4(v, h, l);
        ((ushort4*)(g_Wh + wi * DD * DD))[i] = h;
        ((ushort4*)(g_Wl + wi * DD * DD))[i] = l;
    }
    if (t < NN / 4) ((int4*)g_cnt)[t] = make_int4(0, 0, 0, 0);
    if (t == 0) g_flag = 0;
}

__global__ void k_detect(const unsigned int* __restrict__ words, int E) {
    int i = blockIdx.x * blockDim.x + threadIdx.x;
    if (i < E) {
        if (words[2 * i + 1] != 0u) g_flag = 1;
    }
}

__global__ void k_hist(const void* __restrict__ edges, int E) {
    int is32 = g_flag;
    int e = blockIdx.x * blockDim.x + threadIdx.x;
    if (e < E) {
        int dst = is32 ? ((const int*)edges)[E + e]
                       : (int)((const long long*)edges)[E + e];
        atomicAdd(&g_cnt[dst], 1);
    }
}

// Single-block exclusive scan of g_cnt -> g_rowptr/g_cursor, plus dinv.
__global__ void k_scan() {
    __shared__ int warpsums[32];
    __shared__ int running;
    int tid = threadIdx.x;
    if (tid == 0) running = 0;
    __syncthreads();
    for (int base = 0; base < NN; base += 1024) {
        int i = base + tid;
        int v = (i < NN) ? g_cnt[i] : 0;
        if (i < NN) g_dinv[i] = rsqrtf((float)(v + 1));  // +1 self-loop
        int x = v;
        #pragma unroll
        for (int o = 1; o < 32; o <<= 1) {
            int y = __shfl_up_sync(0xffffffffu, x, o);
            if ((tid & 31) >= o) x += y;
        }
        if ((tid & 31) == 31) warpsums[tid >> 5] = x;
        __syncthreads();
        if (tid < 32) {
            int w = warpsums[tid];
            #pragma unroll
            for (int o = 1; o < 32; o <<= 1) {
                int y = __shfl_up_sync(0xffffffffu, w, o);
                if (tid >= o) w += y;
            }
            warpsums[tid] = w;
        }
        __syncthreads();
        int excl = running + (x - v) + ((tid >= 32) ? warpsums[(tid >> 5) - 1] : 0);
        if (i < NN) { g_rowptr[i] = excl; g_cursor[i] = excl; }
        __syncthreads();
        if (tid == 0) running += warpsums[31];
        __syncthreads();
    }
    if (tid == 0) g_rowptr[NN] = running;
}

__global__ void k_fill(const void* __restrict__ edges, int E) {
    int is32 = g_flag;
    int e = blockIdx.x * blockDim.x + threadIdx.x;
    if (e < E) {
        int src, dst;
        if (is32) {
            src = ((const int*)edges)[e];
            dst = ((const int*)edges)[E + e];
        } else {
            src = (int)((const long long*)edges)[e];
            dst = (int)((const long long*)edges)[E + e];
        }
        int pos = atomicAdd(&g_cursor[dst], 1);
        g_srcs[pos] = src;
    }
}

// ------------------------------ tensor-core GEMM ----------------------------
// H[row] = dinv[row] * (X[row] @ W), fp32-accurate via 2-way bf16 split
// (pre-converted operands) with 3 MMA passes: hh + hl + lh.
// BM=64 rows, BN=128 (full), K=128 fully resident in smem (104 KB -> 2 CTA/SM).
// 8 warps as 2(row) x 4(col): warp tile 32 rows x 32 cols.
__global__ void __launch_bounds__(256, 2)
k_gemm_mma(int layer) {
    extern __shared__ unsigned short sm[];
    unsigned short* Ah = sm;                        // 64 x LDS_PAD
    unsigned short* Al = Ah + 64 * LDS_PAD;
    unsigned short* Bh = Al + 64 * LDS_PAD;         // 128 x LDS_PAD
    unsigned short* Bl = Bh + 128 * LDS_PAD;

    const unsigned short* __restrict__ Whg = g_Wh + layer * DD * DD;
    const unsigned short* __restrict__ Wlg = g_Wl + layer * DD * DD;

    int row0 = blockIdx.x * 64;
    int t = threadIdx.x;

    // load A tile: 64x128 bf16 (hi & lo), 1024 uint4 each, 4 iters
    #pragma unroll
    for (int it = 0; it < 4; it++) {
        int idx = t + it * 256;
        int r = idx >> 4, c = idx & 15;  // c in 8-elem (16B) units
        int grow = row0 + r;
        uint4 vh = make_uint4(0, 0, 0, 0), vl = vh;
        if (grow < NN) {
            vh = *(const uint4*)&g_Xh[grow * DD + c * 8];
            vl = *(const uint4*)&g_Xl[grow * DD + c * 8];
        }
        *(uint4*)&Ah[r * LDS_PAD + c * 8] = vh;
        *(uint4*)&Al[r * LDS_PAD + c * 8] = vl;
    }
    // load B: 128x128 bf16 (hi & lo), 2048 uint4 each, 8 iters
    #pragma unroll
    for (int it = 0; it < 8; it++) {
        int idx = t + it * 256;
        int r = idx >> 4, c = idx & 15;
        *(uint4*)&Bh[r * LDS_PAD + c * 8] = *(const uint4*)&Whg[r * DD + c * 8];
        *(uint4*)&Bl[r * LDS_PAD + c * 8] = *(const uint4*)&Wlg[r * DD + c * 8];
    }
    __syncthreads();

    int lane = t & 31, w = t >> 5;
    int wr = w >> 2, wc = w & 3;
    int arow = wr * 32;
    int bcol = wc * 32;
    int r8 = lane & 7, sub = lane >> 3;

    float acc[2][4][4];
    #pragma unroll
    for (int mi = 0; mi < 2; mi++)
        #pragma unroll
        for (int nj = 0; nj < 4; nj++)
            #pragma unroll
            for (int q = 0; q < 4; q++) acc[mi][nj][q] = 0.f;

    #pragma unroll
    for (int ks = 0; ks < 8; ks++) {
        unsigned int ah[2][4], al[2][4], bh[2][4], bl[2][4];
        #pragma unroll
        for (int mi = 0; mi < 2; mi++) {
            int off = (arow + mi * 16 + (sub & 1) * 8 + r8) * LDS_PAD
                      + ks * 16 + (sub >> 1) * 8;
            ldm_x4(ah[mi], Ah + off);
            ldm_x4(al[mi], Al + off);
        }
        #pragma unroll
        for (int ni = 0; ni < 2; ni++) {
            int off = (ks * 16 + (sub & 1) * 8 + r8) * LDS_PAD
                      + bcol + ni * 16 + (sub >> 1) * 8;
            ldm_x4_t(bh[ni], Bh + off);
            ldm_x4_t(bl[ni], Bl + off);
        }
        #pragma unroll
        for (int mi = 0; mi < 2; mi++) {
            #pragma unroll
            for (int nj = 0; nj < 4; nj++) {
                int ni = nj >> 1, o = (nj & 1) * 2;
                mma16816(acc[mi][nj], ah[mi], bh[ni][o], bh[ni][o + 1]);  // hi*hi
                mma16816(acc[mi][nj], ah[mi], bl[ni][o], bl[ni][o + 1]);  // hi*lo
                mma16816(acc[mi][nj], al[mi], bh[ni][o], bh[ni][o + 1]);  // lo*hi
            }
        }
    }

    // epilogue: scale by dinv[row], store fp32 to g_H
    #pragma unroll
    for (int mi = 0; mi < 2; mi++) {
        int rA = row0 + arow + mi * 16 + (lane >> 2);
        int rB = rA + 8;
        float sA = (rA < NN) ? g_dinv[rA] : 0.f;
        float sB = (rB < NN) ? g_dinv[rB] : 0.f;
        #pragma unroll
        for (int nj = 0; nj < 4; nj++) {
            int col = bcol + nj * 8 + (lane & 3) * 2;
            if (rA < NN)
                *(float2*)&g_H[rA * DD + col] =
                    make_float2(acc[mi][nj][0] * sA, acc[mi][nj][1] * sA);
            if (rB < NN)
                *(float2*)&g_H[rB * DD + col] =
                    make_float2(acc[mi][nj][2] * sB, acc[mi][nj][3] * sB);
        }
    }
}

// --------------------------- aggregation -----------------------------------
// One warp per node, float4 per lane. Writes bf16 hi/lo activations for the
// next GEMM, or fp32 d_out for the final layer.
__global__ void k_agg(const float* __restrict__ bias, float* __restrict__ outExt,
                      int do_relu, int zero0) {
    int gid = blockIdx.x * blockDim.x + threadIdx.x;
    int i = gid >> 5;
    int lane = gid & 31;
    if (i >= NN) return;

    const float4* __restrict__ G = (const float4*)g_H;

    float4 acc = G[i * 32 + lane];  // self-loop term (already dinv[src]-scaled)
    int e = g_rowptr[i];
    int end = g_rowptr[i + 1];
    for (; e + 4 <= end; e += 4) {
        int s0 = g_srcs[e], s1 = g_srcs[e + 1], s2 = g_srcs[e + 2], s3 = g_srcs[e + 3];
        float4 a = G[s0 * 32 + lane];
        float4 b = G[s1 * 32 + lane];
        float4 c = G[s2 * 32 + lane];
        float4 d = G[s3 * 32 + lane];
        acc.x += (a.x + b.x) + (c.x + d.x);
        acc.y += (a.y + b.y) + (c.y + d.y);
        acc.z += (a.z + b.z) + (c.z + d.z);
        acc.w += (a.w + b.w) + (c.w + d.w);
    }
    for (; e < end; e++) {
        int s = g_srcs[e];
        float4 a = G[s * 32 + lane];
        acc.x += a.x; acc.y += a.y; acc.z += a.z; acc.w += a.w;
    }

    float di = g_dinv[i];
    float4 b4 = ((const float4*)bias)[lane];
    float4 o;
    o.x = acc.x * di + b4.x;
    o.y = acc.y * di + b4.y;
    o.z = acc.z * di + b4.z;
    o.w = acc.w * di + b4.w;
    if (do_relu) {
        o.x = fmaxf(o.x, 0.f); o.y = fmaxf(o.y, 0.f);
        o.z = fmaxf(o.z, 0.f); o.w = fmaxf(o.w, 0.f);
    }
    if (outExt) {
        if (zero0 && i == 0) o = make_float4(0.f, 0.f, 0.f, 0.f);
        ((float4*)outExt)[i * 32 + lane] = o;
    } else {
        ushort4 h, l;
        split4(o, h, l);
        ((ushort4*)g_Xh)[i * 32 + lane] = h;
        ((ushort4*)g_Xl)[i * 32 + lane] = l;
    }
}

// ------------------------------- launch -------------------------------------
extern "C" void kernel_launch(void* const* d_in, const int* in_sizes, int n_in,
                              void* d_out, int out_size) {
    const float* emb = (const float*)d_in[0];
    const float* W1  = (const float*)d_in[1];
    const float* b1  = (const float*)d_in[2];
    const float* W2  = (const float*)d_in[3];
    const float* b2  = (const float*)d_in[4];
    const float* W3  = (const float*)d_in[5];
    const float* b3  = (const float*)d_in[6];
    const void*  edges = d_in[7];

    int E = in_sizes[7] / 2;
    if (E > EMAX) E = EMAX;

    const int TB = 256;
    int eBlk = (E + TB - 1) / TB;
    int preBlk = ((NN * DD) / 4 + TB - 1) / TB;  // 6250

    const int GEMM_SMEM = (64 + 64 + 128 + 128) * LDS_PAD * 2;  // 104448 bytes
    cudaFuncSetAttribute(k_gemm_mma, cudaFuncAttributeMaxDynamicSharedMemorySize,
                         GEMM_SMEM);

    k_pre<<<preBlk, TB>>>(emb, W1, W2, W3);
    k_detect<<<eBlk, TB>>>((const unsigned int*)edges, E);
    k_hist<<<eBlk, TB>>>(edges, E);
    k_scan<<<1, 1024>>>();
    k_fill<<<eBlk, TB>>>(edges, E);

    dim3 gemmGrid((NN + 63) / 64);
    int aggBlocks = (NN * 32 + TB - 1) / TB;

    // layer 1
    k_gemm_mma<<<gemmGrid, TB, GEMM_SMEM>>>(0);
    k_agg<<<aggBlocks, TB>>>(b1, nullptr, 1, 0);
    // layer 2
    k_gemm_mma<<<gemmGrid, TB, GEMM_SMEM>>>(1);
    k_agg<<<aggBlocks, TB>>>(b2, nullptr, 1, 0);
    // layer 3 (no relu, zero row 0, write d_out)
    k_gemm_mma<<<gemmGrid, TB, GEMM_SMEM>>>(2);
    k_agg<<<aggBlocks, TB>>>(b3, (float*)d_out, 0, 1);
}

// round 5
// speedup vs baseline: 1.0093x; 1.0093x over previous
#include <cuda_runtime.h>
#include <cuda_bf16.h>

#define NN 50000
#define DD 128
#define EMAX 600000
#define LDS_PAD 136   // bf16 elems per smem row (conflict-mitigating pad)

// ------------- scratch (static device globals; no allocation) -------------
__device__ float          g_H[NN * DD];      // GEMM output, pre-scaled by dinv[row]
__device__ unsigned short g_Xh[NN * DD];     // activations, bf16 hi
__device__ unsigned short g_Xl[NN * DD];     // activations, bf16 lo
__device__ unsigned short g_Wh[3 * DD * DD]; // weights, bf16 hi (3 layers)
__device__ unsigned short g_Wl[3 * DD * DD]; // weights, bf16 lo
__device__ float g_dinv[NN];
__device__ int   g_cnt[NN];
__device__ int   g_rowptr[NN + 1];
__device__ int   g_cursor[NN];
__device__ int   g_srcs[EMAX];
__device__ int   g_flag;           // 1 => edge_index is int32, 0 => int64

// ------------------------------ helpers ------------------------------------
__device__ __forceinline__ void split4(float4 v, ushort4& h, ushort4& l) {
    float f[4] = {v.x, v.y, v.z, v.w};
    unsigned short hh[4], ll[4];
    #pragma unroll
    for (int i = 0; i < 4; i++) {
        __nv_bfloat16 b = __float2bfloat16(f[i]);
        hh[i] = __bfloat16_as_ushort(b);
        ll[i] = __bfloat16_as_ushort(__float2bfloat16(f[i] - __bfloat162float(b)));
    }
    h = make_ushort4(hh[0], hh[1], hh[2], hh[3]);
    l = make_ushort4(ll[0], ll[1], ll[2], ll[3]);
}

__device__ __forceinline__ void ldm_x4(unsigned int r[4], const unsigned short* p) {
    unsigned int addr = (unsigned int)__cvta_generic_to_shared(p);
    asm volatile("ldmatrix.sync.aligned.m8n8.x4.shared.b16 {%0,%1,%2,%3}, [%4];"
                 : "=r"(r[0]), "=r"(r[1]), "=r"(r[2]), "=r"(r[3]) : "r"(addr));
}

__device__ __forceinline__ void ldm_x4_t(unsigned int r[4], const unsigned short* p) {
    unsigned int addr = (unsigned int)__cvta_generic_to_shared(p);
    asm volatile("ldmatrix.sync.aligned.m8n8.x4.trans.shared.b16 {%0,%1,%2,%3}, [%4];"
                 : "=r"(r[0]), "=r"(r[1]), "=r"(r[2]), "=r"(r[3]) : "r"(addr));
}

__device__ __forceinline__ void mma16816(float c[4], const unsigned int a[4],
                                         unsigned int b0, unsigned int b1) {
    asm volatile(
        "mma.sync.aligned.m16n8k16.row.col.f32.bf16.bf16.f32 "
        "{%0,%1,%2,%3}, {%4,%5,%6,%7}, {%8,%9}, {%0,%1,%2,%3};"
        : "+f"(c[0]), "+f"(c[1]), "+f"(c[2]), "+f"(c[3])
        : "r"(a[0]), "r"(a[1]), "r"(a[2]), "r"(a[3]), "r"(b0), "r"(b1));
}

// --------------------------- preprocessing --------------------------------
// Fused: convert emb -> Xh/Xl, convert W1..W3 -> Wh/Wl, zero cnt, zero flag.
__global__ void k_pre(const float* __restrict__ emb,
                      const float* __restrict__ W1,
                      const float* __restrict__ W2,
                      const float* __restrict__ W3) {
    int t = blockIdx.x * blockDim.x + threadIdx.x;
    if (t < (NN * DD) / 4) {
        float4 v = ((const float4*)emb)[t];
        ushort4 h, l;
        split4(v, h, l);
        ((ushort4*)g_Xh)[t] = h;
        ((ushort4*)g_Xl)[t] = l;
    }
    if (t < 3 * (DD * DD / 4)) {
        int wi = t / (DD * DD / 4);
        int i = t - wi * (DD * DD / 4);
        const float* W = (wi == 0) ? W1 : (wi == 1 ? W2 : W3);
        float4 v = ((const float4*)W)[i];
        ushort4 h, l;
        split4(v, h, l);
        ((ushort4*)(g_Wh + wi * DD * DD))[i] = h;
        ((ushort4*)(g_Wl + wi * DD * DD))[i] = l;
    }
    if (t < NN / 4) ((int4*)g_cnt)[t] = make_int4(0, 0, 0, 0);
    if (t == 0) g_flag = 0;
}

__global__ void k_detect(const unsigned int* __restrict__ words, int E) {
    int i = blockIdx.x * blockDim.x + threadIdx.x;
    if (i < E) {
        if (words[2 * i + 1] != 0u) g_flag = 1;
    }
}

__global__ void k_hist(const void* __restrict__ edges, int E) {
    int is32 = g_flag;
    int e = blockIdx.x * blockDim.x + threadIdx.x;
    if (e < E) {
        int dst = is32 ? ((const int*)edges)[E + e]
                       : (int)((const long long*)edges)[E + e];
        atomicAdd(&g_cnt[dst], 1);
    }
}

// Single-block exclusive scan of g_cnt -> g_rowptr/g_cursor, plus dinv.
__global__ void k_scan() {
    __shared__ int warpsums[32];
    __shared__ int running;
    int tid = threadIdx.x;
    if (tid == 0) running = 0;
    __syncthreads();
    for (int base = 0; base < NN; base += 1024) {
        int i = base + tid;
        int v = (i < NN) ? g_cnt[i] : 0;
        if (i < NN) g_dinv[i] = rsqrtf((float)(v + 1));  // +1 self-loop
        int x = v;
        #pragma unroll
        for (int o = 1; o < 32; o <<= 1) {
            int y = __shfl_up_sync(0xffffffffu, x, o);
            if ((tid & 31) >= o) x += y;
        }
        if ((tid & 31) == 31) warpsums[tid >> 5] = x;
        __syncthreads();
        if (tid < 32) {
            int w = warpsums[tid];
            #pragma unroll
            for (int o = 1; o < 32; o <<= 1) {
                int y = __shfl_up_sync(0xffffffffu, w, o);
                if (tid >= o) w += y;
            }
            warpsums[tid] = w;
        }
        __syncthreads();
        int excl = running + (x - v) + ((tid >= 32) ? warpsums[(tid >> 5) - 1] : 0);
        if (i < NN) { g_rowptr[i] = excl; g_cursor[i] = excl; }
        __syncthreads();
        if (tid == 0) running += warpsums[31];
        __syncthreads();
    }
    if (tid == 0) g_rowptr[NN] = running;
}

__global__ void k_fill(const void* __restrict__ edges, int E) {
    int is32 = g_flag;
    int e = blockIdx.x * blockDim.x + threadIdx.x;
    if (e < E) {
        int src, dst;
        if (is32) {
            src = ((const int*)edges)[e];
            dst = ((const int*)edges)[E + e];
        } else {
            src = (int)((const long long*)edges)[e];
            dst = (int)((const long long*)edges)[E + e];
        }
        int pos = atomicAdd(&g_cursor[dst], 1);
        g_srcs[pos] = src;
    }
}

// ------------------------------ tensor-core GEMM ----------------------------
// H[row] = dinv[row] * (X[row] @ W), fp32-accurate via 2-way bf16 split
// (pre-converted operands) with 3 MMA passes: hh + hl + lh.
// BM=64 rows, BN=128 (full), K=128 fully resident in smem (104 KB -> 2 CTA/SM).
// 8 warps as 2(row) x 4(col): warp tile 32 rows x 32 cols.
__global__ void __launch_bounds__(256, 2)
k_gemm_mma(int layer) {
    extern __shared__ unsigned short sm[];
    unsigned short* Ah = sm;                        // 64 x LDS_PAD
    unsigned short* Al = Ah + 64 * LDS_PAD;
    unsigned short* Bh = Al + 64 * LDS_PAD;         // 128 x LDS_PAD
    unsigned short* Bl = Bh + 128 * LDS_PAD;

    const unsigned short* __restrict__ Whg = g_Wh + layer * DD * DD;
    const unsigned short* __restrict__ Wlg = g_Wl + layer * DD * DD;

    int row0 = blockIdx.x * 64;
    int t = threadIdx.x;

    // load A tile: 64x128 bf16 (hi & lo), 1024 uint4 each, 4 iters
    #pragma unroll
    for (int it = 0; it < 4; it++) {
        int idx = t + it * 256;
        int r = idx >> 4, c = idx & 15;  // c in 8-elem (16B) units
        int grow = row0 + r;
        uint4 vh = make_uint4(0, 0, 0, 0), vl = vh;
        if (grow < NN) {
            vh = *(const uint4*)&g_Xh[grow * DD + c * 8];
            vl = *(const uint4*)&g_Xl[grow * DD + c * 8];
        }
        *(uint4*)&Ah[r * LDS_PAD + c * 8] = vh;
        *(uint4*)&Al[r * LDS_PAD + c * 8] = vl;
    }
    // load B: 128x128 bf16 (hi & lo), 2048 uint4 each, 8 iters
    #pragma unroll
    for (int it = 0; it < 8; it++) {
        int idx = t + it * 256;
        int r = idx >> 4, c = idx & 15;
        *(uint4*)&Bh[r * LDS_PAD + c * 8] = *(const uint4*)&Whg[r * DD + c * 8];
        *(uint4*)&Bl[r * LDS_PAD + c * 8] = *(const uint4*)&Wlg[r * DD + c * 8];
    }
    __syncthreads();

    int lane = t & 31, w = t >> 5;
    int wr = w >> 2, wc = w & 3;
    int arow = wr * 32;
    int bcol = wc * 32;
    int r8 = lane & 7, sub = lane >> 3;

    float acc[2][4][4];
    #pragma unroll
    for (int mi = 0; mi < 2; mi++)
        #pragma unroll
        for (int nj = 0; nj < 4; nj++)
            #pragma unroll
            for (int q = 0; q < 4; q++) acc[mi][nj][q] = 0.f;

    #pragma unroll
    for (int ks = 0; ks < 8; ks++) {
        unsigned int ah[2][4], al[2][4], bh[2][4], bl[2][4];
        #pragma unroll
        for (int mi = 0; mi < 2; mi++) {
            int off = (arow + mi * 16 + (sub & 1) * 8 + r8) * LDS_PAD
                      + ks * 16 + (sub >> 1) * 8;
            ldm_x4(ah[mi], Ah + off);
            ldm_x4(al[mi], Al + off);
        }
        #pragma unroll
        for (int ni = 0; ni < 2; ni++) {
            int off = (ks * 16 + (sub & 1) * 8 + r8) * LDS_PAD
                      + bcol + ni * 16 + (sub >> 1) * 8;
            ldm_x4_t(bh[ni], Bh + off);
            ldm_x4_t(bl[ni], Bl + off);
        }
        #pragma unroll
        for (int mi = 0; mi < 2; mi++) {
            #pragma unroll
            for (int nj = 0; nj < 4; nj++) {
                int ni = nj >> 1, o = (nj & 1) * 2;
                mma16816(acc[mi][nj], ah[mi], bh[ni][o], bh[ni][o + 1]);  // hi*hi
                mma16816(acc[mi][nj], ah[mi], bl[ni][o], bl[ni][o + 1]);  // hi*lo
                mma16816(acc[mi][nj], al[mi], bh[ni][o], bh[ni][o + 1]);  // lo*hi
            }
        }
    }

    // epilogue: scale by dinv[row], store fp32 to g_H
    #pragma unroll
    for (int mi = 0; mi < 2; mi++) {
        int rA = row0 + arow + mi * 16 + (lane >> 2);
        int rB = rA + 8;
        float sA = (rA < NN) ? g_dinv[rA] : 0.f;
        float sB = (rB < NN) ? g_dinv[rB] : 0.f;
        #pragma unroll
        for (int nj = 0; nj < 4; nj++) {
            int col = bcol + nj * 8 + (lane & 3) * 2;
            if (rA < NN)
                *(float2*)&g_H[rA * DD + col] =
                    make_float2(acc[mi][nj][0] * sA, acc[mi][nj][1] * sA);
            if (rB < NN)
                *(float2*)&g_H[rB * DD + col] =
                    make_float2(acc[mi][nj][2] * sB, acc[mi][nj][3] * sB);
        }
    }
}

// --------------------------- aggregation -----------------------------------
// One warp per node, float4 per lane. Writes bf16 hi/lo activations for the
// next GEMM, or fp32 d_out for the final layer.
__global__ void k_agg(const float* __restrict__ bias, float* __restrict__ outExt,
                      int do_relu, int zero0) {
    int gid = blockIdx.x * blockDim.x + threadIdx.x;
    int i = gid >> 5;
    int lane = gid & 31;
    if (i >= NN) return;

    const float4* __restrict__ G = (const float4*)g_H;

    float4 acc = G[i * 32 + lane];  // self-loop term (already dinv[src]-scaled)
    int e = g_rowptr[i];
    int end = g_rowptr[i + 1];
    for (; e + 4 <= end; e += 4) {
        int s0 = g_srcs[e], s1 = g_srcs[e + 1], s2 = g_srcs[e + 2], s3 = g_srcs[e + 3];
        float4 a = G[s0 * 32 + lane];
        float4 b = G[s1 * 32 + lane];
        float4 c = G[s2 * 32 + lane];
        float4 d = G[s3 * 32 + lane];
        acc.x += (a.x + b.x) + (c.x + d.x);
        acc.y += (a.y + b.y) + (c.y + d.y);
        acc.z += (a.z + b.z) + (c.z + d.z);
        acc.w += (a.w + b.w) + (c.w + d.w);
    }
    for (; e < end; e++) {
        int s = g_srcs[e];
        float4 a = G[s * 32 + lane];
        acc.x += a.x; acc.y += a.y; acc.z += a.z; acc.w += a.w;
    }

    float di = g_dinv[i];
    float4 b4 = ((const float4*)bias)[lane];
    float4 o;
    o.x = acc.x * di + b4.x;
    o.y = acc.y * di + b4.y;
    o.z = acc.z * di + b4.z;
    o.w = acc.w * di + b4.w;
    if (do_relu) {
        o.x = fmaxf(o.x, 0.f); o.y = fmaxf(o.y, 0.f);
        o.z = fmaxf(o.z, 0.f); o.w = fmaxf(o.w, 0.f);
    }
    if (outExt) {
        if (zero0 && i == 0) o = make_float4(0.f, 0.f, 0.f, 0.f);
        ((float4*)outExt)[i * 32 + lane] = o;
    } else {
        ushort4 h, l;
        split4(o, h, l);
        ((ushort4*)g_Xh)[i * 32 + lane] = h;
        ((ushort4*)g_Xl)[i * 32 + lane] = l;
    }
}

// ------------------------------- launch -------------------------------------
extern "C" void kernel_launch(void* const* d_in, const int* in_sizes, int n_in,
                              void* d_out, int out_size) {
    const float* emb = (const float*)d_in[0];
    const float* W1  = (const float*)d_in[1];
    const float* b1  = (const float*)d_in[2];
    const float* W2  = (const float*)d_in[3];
    const float* b2  = (const float*)d_in[4];
    const float* W3  = (const float*)d_in[5];
    const float* b3  = (const float*)d_in[6];
    const void*  edges = d_in[7];

    int E = in_sizes[7] / 2;
    if (E > EMAX) E = EMAX;

    const int TB = 256;
    int eBlk = (E + TB - 1) / TB;
    int preBlk = ((NN * DD) / 4 + TB - 1) / TB;  // 6250

    const int GEMM_SMEM = (64 + 64 + 128 + 128) * LDS_PAD * 2;  // 104448 bytes
    cudaFuncSetAttribute(k_gemm_mma, cudaFuncAttributeMaxDynamicSharedMemorySize,
                         GEMM_SMEM);

    k_pre<<<preBlk, TB>>>(emb, W1, W2, W3);
    k_detect<<<eBlk, TB>>>((const unsigned int*)edges, E);
    k_hist<<<eBlk, TB>>>(edges, E);
    k_scan<<<1, 1024>>>();
    k_fill<<<eBlk, TB>>>(edges, E);

    dim3 gemmGrid((NN + 63) / 64);
    int aggBlocks = (NN * 32 + TB - 1) / TB;

    // layer 1
    k_gemm_mma<<<gemmGrid, TB, GEMM_SMEM>>>(0);
    k_agg<<<aggBlocks, TB>>>(b1, nullptr, 1, 0);
    // layer 2
    k_gemm_mma<<<gemmGrid, TB, GEMM_SMEM>>>(1);
    k_agg<<<aggBlocks, TB>>>(b2, nullptr, 1, 0);
    // layer 3 (no relu, zero row 0, write d_out)
    k_gemm_mma<<<gemmGrid, TB, GEMM_SMEM>>>(2);
    k_agg<<<aggBlocks, TB>>>(b3, (float*)d_out, 0, 1);
}